// round 3
// baseline (speedup 1.0000x reference)
#include <cuda_runtime.h>
#include <math.h>

// Problem constants
#define BATCH 8
#define NPTS  8192
#define SPTS  2048
#define C1V   128
#define C2V   256
#define MROWS 65536          // BATCH*NPTS
#define K1V   384            // C1+C2
#define N1V   256
#define K2V   256
#define N2V   128
#define ROWTILES 512         // MROWS/128
#define SPAD 136             // padded smem row stride (floats), kills STS conflicts

// Scratch (device globals: allocation-free)
__device__ float g_X [(size_t)MROWS * K1V];
__device__ float g_Y1[(size_t)MROWS * N1V];
__device__ float g_Y2[(size_t)MROWS * N2V];
__device__ int   g_idx[MROWS * 3];
__device__ float g_wt [MROWS * 3];
__device__ float g_ps1[ROWTILES * N1V], g_pq1[ROWTILES * N1V];
__device__ float g_ps2[ROWTILES * N2V], g_pq2[ROWTILES * N2V];
__device__ float g_sc1[N1V], g_sh1[N1V];
__device__ float g_sc2[N2V], g_sh2[N2V];

// ---------------------------------------------------------------------------
// Kernel 1: 3-nearest-neighbor search + interpolation weights.
// ---------------------------------------------------------------------------
__global__ void nn3_kernel(const float* __restrict__ xyz1,
                           const float* __restrict__ xyz2)
{
    __shared__ float4 s2[SPTS];
    const int b = blockIdx.y;
    const float* x2 = xyz2 + (size_t)b * SPTS * 3;
    for (int i = threadIdx.x; i < SPTS; i += blockDim.x) {
        float x = x2[i*3+0], y = x2[i*3+1], z = x2[i*3+2];
        s2[i] = make_float4(x, y, z, x*x + y*y + z*z);
    }
    __syncthreads();

    const int n = blockIdx.x * blockDim.x + threadIdx.x;
    const int p = b * NPTS + n;
    const float ax = xyz1[(size_t)p*3+0];
    const float ay = xyz1[(size_t)p*3+1];
    const float az = xyz1[(size_t)p*3+2];
    const float an = ax*ax + ay*ay + az*az;

    float d0 = 1e30f, d1 = 1e30f, d2 = 1e30f;
    int   j0 = 0,     j1 = 0,     j2 = 0;
    #pragma unroll 4
    for (int s = 0; s < SPTS; s++) {
        float4 q = s2[s];
        float dd = an + q.w - 2.0f * (ax*q.x + ay*q.y + az*q.z);
        if (dd < d2) {
            if (dd < d1) {
                if (dd < d0) { d2=d1; j2=j1; d1=d0; j1=j0; d0=dd; j0=s; }
                else         { d2=d1; j2=j1; d1=dd; j1=s; }
            } else           { d2=dd; j2=s; }
        }
    }
    float e0 = sqrtf(fmaxf(d0, 0.0f));
    float e1 = sqrtf(fmaxf(d1, 0.0f));
    float e2 = sqrtf(fmaxf(d2, 0.0f));
    float r0 = 1.0f / (e0 + 1e-8f);
    float r1 = 1.0f / (e1 + 1e-8f);
    float r2 = 1.0f / (e2 + 1e-8f);
    float inv = 1.0f / (r0 + r1 + r2);
    g_wt[p*3+0] = r0*inv; g_wt[p*3+1] = r1*inv; g_wt[p*3+2] = r2*inv;
    g_idx[p*3+0] = j0;    g_idx[p*3+1] = j1;    g_idx[p*3+2] = j2;
}

// ---------------------------------------------------------------------------
// Kernel 2: build X = [points1 | sum_k w_k * points2[idx_k]]  ([MROWS, 384])
// ---------------------------------------------------------------------------
__global__ void gather_concat_kernel(const float* __restrict__ points1,
                                     const float* __restrict__ points2)
{
    const int warp = threadIdx.x >> 5;
    const int lane = threadIdx.x & 31;
    const int p = blockIdx.x * 8 + warp;
    const int b = p >> 13;

    const int   i0 = g_idx[p*3+0], i1 = g_idx[p*3+1], i2 = g_idx[p*3+2];
    const float w0 = g_wt[p*3+0],  w1 = g_wt[p*3+1],  w2 = g_wt[p*3+2];

    const float4* p1 = (const float4*)(points1 + (size_t)p * C1V);
    float4* Xr = (float4*)(g_X + (size_t)p * K1V);
    Xr[lane] = p1[lane];

    const float4* pa = (const float4*)(points2 + ((size_t)b*SPTS + i0) * C2V);
    const float4* pb = (const float4*)(points2 + ((size_t)b*SPTS + i1) * C2V);
    const float4* pc = (const float4*)(points2 + ((size_t)b*SPTS + i2) * C2V);
    #pragma unroll
    for (int t = 0; t < 2; t++) {
        int c = t*32 + lane;
        float4 va = pa[c], vb = pb[c], vc = pc[c];
        float4 o;
        o.x = w0*va.x + w1*vb.x + w2*vc.x;
        o.y = w0*va.y + w1*vb.y + w2*vc.y;
        o.z = w0*va.z + w1*vb.z + w2*vc.z;
        o.w = w0*va.w + w1*vb.w + w2*vc.w;
        Xr[32 + c] = o;
    }
}

// ---------------------------------------------------------------------------
// Kernel 3/5: SGEMM  Y[M,N] = op(A)[M,K] @ W[N,K]^T + bias, double-buffered.
// 128x128 tile, BK=16, 8x8 per thread, 256 threads, 2 CTAs/SM.
// TRANS_A fuses relu(a*scale[k]+shift[k]) into the A-tile global load.
// Epilogue writes deterministic per-row-tile column sum / sumsq partials.
// ---------------------------------------------------------------------------
template<bool TRANS_A>
__global__ void __launch_bounds__(256, 2)
sgemm_kernel(const float* __restrict__ A,     // [M,K]
             const float* __restrict__ W,     // [N,K]
             const float* __restrict__ bias,  // [N]
             const float* __restrict__ aScale,// [K] (TRANS_A only)
             const float* __restrict__ aShift,// [K]
             float* __restrict__ Y,           // [M,N]
             float* __restrict__ psum,        // [M/128, N]
             float* __restrict__ psq,         // [M/128, N]
             int K, int N)
{
    __shared__ float As[2][16][SPAD];
    __shared__ float Bs[2][16][SPAD];
    __shared__ float sSc[K1V];
    __shared__ float sSh[K1V];

    const int tid = threadIdx.x;
    const int tx = tid & 15;
    const int ty = tid >> 4;
    const int bx = blockIdx.x;
    const int by = blockIdx.y;
    const int lr = tid >> 2;          // 0..63 base row within half-tile
    const int lq = tid & 3;           // float4 slot within 16-k chunk

    if (TRANS_A) {
        for (int i = tid; i < K; i += 256) { sSc[i] = aScale[i]; sSh[i] = aShift[i]; }
        __syncthreads();
    }

    float acc[8][8];
    #pragma unroll
    for (int i = 0; i < 8; i++)
        #pragma unroll
        for (int j = 0; j < 8; j++) acc[i][j] = 0.0f;

    const float* Ab = A + (size_t)by * 128 * K;
    const float* Wb = W + (size_t)bx * 128 * K;

    float4 av[2], wv[2];

    // load tile k0 into registers (TRANS_A transform applied here)
    auto load_tiles = [&](int k0) {
        #pragma unroll
        for (int i = 0; i < 2; i++) {
            int r = i*64 + lr;
            float4 v = *(const float4*)(Ab + (size_t)r*K + k0 + lq*4);
            if (TRANS_A) {
                int kb = k0 + lq*4;
                v.x = fmaxf(fmaf(v.x, sSc[kb+0], sSh[kb+0]), 0.0f);
                v.y = fmaxf(fmaf(v.y, sSc[kb+1], sSh[kb+1]), 0.0f);
                v.z = fmaxf(fmaf(v.z, sSc[kb+2], sSh[kb+2]), 0.0f);
                v.w = fmaxf(fmaf(v.w, sSc[kb+3], sSh[kb+3]), 0.0f);
            }
            av[i] = v;
            wv[i] = *(const float4*)(Wb + (size_t)r*K + k0 + lq*4);
        }
    };
    auto store_tiles = [&](int buf) {
        #pragma unroll
        for (int i = 0; i < 2; i++) {
            int r = i*64 + lr;
            As[buf][lq*4+0][r] = av[i].x; As[buf][lq*4+1][r] = av[i].y;
            As[buf][lq*4+2][r] = av[i].z; As[buf][lq*4+3][r] = av[i].w;
            Bs[buf][lq*4+0][r] = wv[i].x; Bs[buf][lq*4+1][r] = wv[i].y;
            Bs[buf][lq*4+2][r] = wv[i].z; Bs[buf][lq*4+3][r] = wv[i].w;
        }
    };

    const int KT = K >> 4;
    load_tiles(0);
    store_tiles(0);
    __syncthreads();

    for (int kt = 0; kt < KT; kt++) {
        const int buf = kt & 1;
        if (kt + 1 < KT) load_tiles((kt + 1) << 4);
        #pragma unroll
        for (int kk = 0; kk < 16; kk++) {
            float a[8], bb[8];
            *(float4*)&a[0]  = *(const float4*)&As[buf][kk][ty*8];
            *(float4*)&a[4]  = *(const float4*)&As[buf][kk][ty*8+4];
            *(float4*)&bb[0] = *(const float4*)&Bs[buf][kk][tx*8];
            *(float4*)&bb[4] = *(const float4*)&Bs[buf][kk][tx*8+4];
            #pragma unroll
            for (int i = 0; i < 8; i++)
                #pragma unroll
                for (int j = 0; j < 8; j++)
                    acc[i][j] = fmaf(a[i], bb[j], acc[i][j]);
        }
        if (kt + 1 < KT) {
            store_tiles((kt + 1) & 1);
            __syncthreads();
        }
    }

    // Epilogue: bias, store Y, per-tile column partials for BN stats.
    const int colBase = bx*128 + tx*8;
    const int rowBase = by*128 + ty*8;
    float bsv[8];
    #pragma unroll
    for (int j = 0; j < 8; j++) bsv[j] = bias[colBase + j];
    float ps[8], pq[8];
    #pragma unroll
    for (int j = 0; j < 8; j++) { ps[j] = 0.0f; pq[j] = 0.0f; }

    #pragma unroll
    for (int i = 0; i < 8; i++) {
        float t0[8];
        #pragma unroll
        for (int j = 0; j < 8; j++) {
            float yv = acc[i][j] + bsv[j];
            t0[j] = yv;
            ps[j] += yv;
            pq[j] = fmaf(yv, yv, pq[j]);
        }
        float* Yr = Y + (size_t)(rowBase + i) * N + colBase;
        ((float4*)Yr)[0] = make_float4(t0[0], t0[1], t0[2], t0[3]);
        ((float4*)Yr)[1] = make_float4(t0[4], t0[5], t0[6], t0[7]);
    }

    __syncthreads();                       // reuse smem as 16x128 reduction space
    float* redS = &As[0][0][0];
    float* redQ = &Bs[0][0][0];
    #pragma unroll
    for (int j = 0; j < 8; j++) {
        redS[ty*128 + tx*8 + j] = ps[j];
        redQ[ty*128 + tx*8 + j] = pq[j];
    }
    __syncthreads();
    if (tid < 128) {
        float s = 0.0f, q = 0.0f;
        #pragma unroll
        for (int t = 0; t < 16; t++) { s += redS[t*128 + tid]; q += redQ[t*128 + tid]; }
        psum[(size_t)by * N + bx*128 + tid] = s;
        psq [(size_t)by * N + bx*128 + tid] = q;
    }
}

// ---------------------------------------------------------------------------
// Kernel 4/6: reduce partials -> BN scale/shift per channel.
// Block = 256 threads = 64 channels x 4 row-parts. Coalesced loads, MLP via
// unroll, deterministic fixed-order smem tree combine.
// ---------------------------------------------------------------------------
__global__ void bn_stats_kernel(const float* __restrict__ psum,
                                const float* __restrict__ psq,
                                int N,
                                const float* __restrict__ g,
                                const float* __restrict__ beta,
                                float* __restrict__ scale,
                                float* __restrict__ shift)
{
    __shared__ float ss[4][64];
    __shared__ float sq[4][64];
    const int cl   = threadIdx.x & 63;
    const int part = threadIdx.x >> 6;            // 0..3
    const int c    = blockIdx.x * 64 + cl;
    const int r0   = part * (ROWTILES / 4);       // 128 rows per part

    float s0 = 0.f, s1 = 0.f, q0 = 0.f, q1 = 0.f;
    #pragma unroll 8
    for (int r = 0; r < ROWTILES / 4; r += 2) {
        s0 += psum[(size_t)(r0 + r)     * N + c];
        s1 += psum[(size_t)(r0 + r + 1) * N + c];
        q0 += psq [(size_t)(r0 + r)     * N + c];
        q1 += psq [(size_t)(r0 + r + 1) * N + c];
    }
    ss[part][cl] = s0 + s1;
    sq[part][cl] = q0 + q1;
    __syncthreads();

    if (part == 0) {
        double s = (double)ss[0][cl] + (double)ss[1][cl]
                 + (double)ss[2][cl] + (double)ss[3][cl];
        double q = (double)sq[0][cl] + (double)sq[1][cl]
                 + (double)sq[2][cl] + (double)sq[3][cl];
        double mu  = s / (double)MROWS;
        double var = q / (double)MROWS - mu * mu;
        float sc = g[c] / sqrtf((float)var + 1e-5f);
        scale[c] = sc;
        shift[c] = beta[c] - (float)mu * sc;
    }
}

// ---------------------------------------------------------------------------
// Kernel 7: out = relu(Y2 * scale2 + shift2), float4-vectorized.
// ---------------------------------------------------------------------------
__global__ void bn_relu_out_kernel(const float* __restrict__ Y,
                                   float* __restrict__ out)
{
    int i = blockIdx.x * blockDim.x + threadIdx.x;
    const float4 v = ((const float4*)Y)[i];
    int c = (i * 4) & (N2V - 1);
    float4 o;
    o.x = fmaxf(fmaf(v.x, g_sc2[c+0], g_sh2[c+0]), 0.0f);
    o.y = fmaxf(fmaf(v.y, g_sc2[c+1], g_sh2[c+1]), 0.0f);
    o.z = fmaxf(fmaf(v.z, g_sc2[c+2], g_sh2[c+2]), 0.0f);
    o.w = fmaxf(fmaf(v.w, g_sc2[c+3], g_sh2[c+3]), 0.0f);
    ((float4*)out)[i] = o;
}

// ---------------------------------------------------------------------------
// Launcher (graph-capturable: kernel launches only)
// ---------------------------------------------------------------------------
extern "C" void kernel_launch(void* const* d_in, const int* in_sizes, int n_in,
                              void* d_out, int out_size)
{
    const float* xyz1    = (const float*)d_in[0];
    const float* xyz2    = (const float*)d_in[1];
    const float* points1 = (const float*)d_in[2];
    const float* points2 = (const float*)d_in[3];
    const float* w1      = (const float*)d_in[4];
    const float* b1      = (const float*)d_in[5];
    const float* g1      = (const float*)d_in[6];
    const float* beta1   = (const float*)d_in[7];
    const float* w2      = (const float*)d_in[8];
    const float* b2      = (const float*)d_in[9];
    const float* g2      = (const float*)d_in[10];
    const float* beta2   = (const float*)d_in[11];
    float* out = (float*)d_out;

    float *pX, *pY1, *pY2, *pps1, *ppq1, *pps2, *ppq2, *psc1, *psh1, *psc2, *psh2;
    cudaGetSymbolAddress((void**)&pX,   g_X);
    cudaGetSymbolAddress((void**)&pY1,  g_Y1);
    cudaGetSymbolAddress((void**)&pY2,  g_Y2);
    cudaGetSymbolAddress((void**)&pps1, g_ps1);
    cudaGetSymbolAddress((void**)&ppq1, g_pq1);
    cudaGetSymbolAddress((void**)&pps2, g_ps2);
    cudaGetSymbolAddress((void**)&ppq2, g_pq2);
    cudaGetSymbolAddress((void**)&psc1, g_sc1);
    cudaGetSymbolAddress((void**)&psh1, g_sh1);
    cudaGetSymbolAddress((void**)&psc2, g_sc2);
    cudaGetSymbolAddress((void**)&psh2, g_sh2);

    nn3_kernel<<<dim3(NPTS/256, BATCH), 256>>>(xyz1, xyz2);
    gather_concat_kernel<<<MROWS/8, 256>>>(points1, points2);
    sgemm_kernel<false><<<dim3(N1V/128, MROWS/128), 256>>>(
        pX, w1, b1, nullptr, nullptr, pY1, pps1, ppq1, K1V, N1V);
    bn_stats_kernel<<<N1V/64, 256>>>(pps1, ppq1, N1V, g1, beta1, psc1, psh1);
    sgemm_kernel<true><<<dim3(N2V/128, MROWS/128), 256>>>(
        pY1, w2, b2, psc1, psh1, pY2, pps2, ppq2, K2V, N2V);
    bn_stats_kernel<<<N2V/64, 256>>>(pps2, ppq2, N2V, g2, beta2, psc2, psh2);
    bn_relu_out_kernel<<<(MROWS * N2V / 4) / 256, 256>>>(pY2, out);
}

// round 5
// speedup vs baseline: 1.1717x; 1.1717x over previous
#include <cuda_runtime.h>
#include <math.h>
#include <stdint.h>

// Problem constants
#define BATCH 8
#define NPTS  8192
#define SPTS  2048
#define C1V   128
#define C2V   256
#define MROWS 65536
#define K1V   384
#define N1V   256
#define K2V   256
#define N2V   128
#define RPARTS 256            // row partitions for BN stats stage 1

// Scratch (device globals: allocation-free)
__device__ float g_X [(size_t)MROWS * K1V];
__device__ float g_Y1[(size_t)MROWS * N1V];
__device__ float g_Y2[(size_t)MROWS * N2V];
__device__ int   g_idx[MROWS * 3];
__device__ float g_wt [MROWS * 3];
__device__ float g_ps1[RPARTS * N1V], g_pq1[RPARTS * N1V];
__device__ float g_ps2[RPARTS * N2V], g_pq2[RPARTS * N2V];
__device__ float g_sc1[N1V], g_sh1[N1V];
__device__ float g_sc2[N2V], g_sh2[N2V];

// ---------------------------------------------------------------------------
// tf32 helpers (portable PTX, no sm_103a-only features)
// ---------------------------------------------------------------------------
__device__ __forceinline__ void split_tf32(float f, uint32_t& h, uint32_t& l) {
    asm("cvt.rna.tf32.f32 %0, %1;" : "=r"(h) : "f"(f));
    float lo = f - __uint_as_float(h);
    asm("cvt.rna.tf32.f32 %0, %1;" : "=r"(l) : "f"(lo));
}
// D += A(16x8) * B(8x8), tf32 inputs, fp32 accum
__device__ __forceinline__ void mma8(float* c, const uint32_t* a, const uint32_t* b) {
    asm volatile(
        "mma.sync.aligned.m16n8k8.row.col.f32.tf32.tf32.f32 "
        "{%0,%1,%2,%3}, {%4,%5,%6,%7}, {%8,%9}, {%0,%1,%2,%3};"
        : "+f"(c[0]), "+f"(c[1]), "+f"(c[2]), "+f"(c[3])
        : "r"(a[0]), "r"(a[1]), "r"(a[2]), "r"(a[3]), "r"(b[0]), "r"(b[1]));
}

// ---------------------------------------------------------------------------
// Kernel 1: 3-NN + interpolation weights
// ---------------------------------------------------------------------------
__global__ void nn3_kernel(const float* __restrict__ xyz1,
                           const float* __restrict__ xyz2)
{
    __shared__ float4 s2[SPTS];
    const int b = blockIdx.y;
    const float* x2 = xyz2 + (size_t)b * SPTS * 3;
    for (int i = threadIdx.x; i < SPTS; i += blockDim.x) {
        float x = x2[i*3+0], y = x2[i*3+1], z = x2[i*3+2];
        s2[i] = make_float4(x, y, z, x*x + y*y + z*z);
    }
    __syncthreads();

    const int n = blockIdx.x * blockDim.x + threadIdx.x;
    const int p = b * NPTS + n;
    const float ax = xyz1[(size_t)p*3+0];
    const float ay = xyz1[(size_t)p*3+1];
    const float az = xyz1[(size_t)p*3+2];
    const float an = ax*ax + ay*ay + az*az;

    float d0 = 1e30f, d1 = 1e30f, d2 = 1e30f;
    int   j0 = 0,     j1 = 0,     j2 = 0;
    #pragma unroll 4
    for (int s = 0; s < SPTS; s++) {
        float4 q = s2[s];
        float dd = an + q.w - 2.0f * (ax*q.x + ay*q.y + az*q.z);
        if (dd < d2) {
            if (dd < d1) {
                if (dd < d0) { d2=d1; j2=j1; d1=d0; j1=j0; d0=dd; j0=s; }
                else         { d2=d1; j2=j1; d1=dd; j1=s; }
            } else           { d2=dd; j2=s; }
        }
    }
    float e0 = sqrtf(fmaxf(d0, 0.0f));
    float e1 = sqrtf(fmaxf(d1, 0.0f));
    float e2 = sqrtf(fmaxf(d2, 0.0f));
    float r0 = 1.0f / (e0 + 1e-8f);
    float r1 = 1.0f / (e1 + 1e-8f);
    float r2 = 1.0f / (e2 + 1e-8f);
    float inv = 1.0f / (r0 + r1 + r2);
    g_wt[p*3+0] = r0*inv; g_wt[p*3+1] = r1*inv; g_wt[p*3+2] = r2*inv;
    g_idx[p*3+0] = j0;    g_idx[p*3+1] = j1;    g_idx[p*3+2] = j2;
}

// ---------------------------------------------------------------------------
// Kernel 2: X = [points1 | interp(points2)]  ([MROWS, 384])
// ---------------------------------------------------------------------------
__global__ void gather_concat_kernel(const float* __restrict__ points1,
                                     const float* __restrict__ points2)
{
    const int warp = threadIdx.x >> 5;
    const int lane = threadIdx.x & 31;
    const int p = blockIdx.x * 8 + warp;
    const int b = p >> 13;

    const int   i0 = g_idx[p*3+0], i1 = g_idx[p*3+1], i2 = g_idx[p*3+2];
    const float w0 = g_wt[p*3+0],  w1 = g_wt[p*3+1],  w2 = g_wt[p*3+2];

    const float4* p1 = (const float4*)(points1 + (size_t)p * C1V);
    float4* Xr = (float4*)(g_X + (size_t)p * K1V);
    Xr[lane] = p1[lane];

    const float4* pa = (const float4*)(points2 + ((size_t)b*SPTS + i0) * C2V);
    const float4* pb = (const float4*)(points2 + ((size_t)b*SPTS + i1) * C2V);
    const float4* pc = (const float4*)(points2 + ((size_t)b*SPTS + i2) * C2V);
    #pragma unroll
    for (int t = 0; t < 2; t++) {
        int c = t*32 + lane;
        float4 va = pa[c], vb = pb[c], vc = pc[c];
        float4 o;
        o.x = w0*va.x + w1*vb.x + w2*vc.x;
        o.y = w0*va.y + w1*vb.y + w2*vc.y;
        o.z = w0*va.z + w1*vb.z + w2*vc.z;
        o.w = w0*va.w + w1*vb.w + w2*vc.w;
        Xr[32 + c] = o;
    }
}

// ---------------------------------------------------------------------------
// tf32 mma.sync GEMM with 3x error-compensated split:
//   Y[M rows, N cols] = op(A)[M,K] @ W[N,K]^T + bias
// CTA tile 128x128 (grid.x = N/128, grid.y = M/128), BK=16, 8 warps, warp
// tile 32x64 (2 m16-tiles x 8 n8-tiles). hi/lo tf32 split applied at the
// smem store; double-buffered with register prefetch.
// smem tiles: Ah|Al|Bh|Bl, each [128][20] floats (pad kills LDS conflicts).
// TRANS_A fuses relu(a*scale+shift) (previous BN) into the A global load.
// ---------------------------------------------------------------------------
template<int KDIM, bool TRANS_A>
__global__ void __launch_bounds__(256, 1)
gemm_mma(const float* __restrict__ A,
         const float* __restrict__ W,
         const float* __restrict__ bias,
         const float* __restrict__ aScale,
         const float* __restrict__ aShift,
         float* __restrict__ Y, int N)
{
    extern __shared__ float sm[];
    float* sSc  = sm;                  // [384]
    float* sSh  = sm + 384;            // [384]
    float* tiles = sm + 768;           // 2 bufs x 4 arrays x 2560 floats

    const int tid  = threadIdx.x;
    const int wid  = tid >> 5;
    const int lane = tid & 31;
    const int g    = lane >> 2;        // 0..7
    const int t    = lane & 3;         // 0..3
    const int wm   = (wid & 3) * 32;   // warp m offset in CTA tile
    const int wn   = (wid >> 2) * 64;  // warp n offset

    if (TRANS_A) {
        for (int i = tid; i < KDIM; i += 256) { sSc[i] = aScale[i]; sSh[i] = aShift[i]; }
        __syncthreads();
    }

    float acc[2][8][4];
    #pragma unroll
    for (int mt = 0; mt < 2; mt++)
        #pragma unroll
        for (int nt = 0; nt < 8; nt++)
            #pragma unroll
            for (int j = 0; j < 4; j++) acc[mt][nt][j] = 0.0f;

    const float* Ab = A + (size_t)blockIdx.y * 128 * KDIM;
    const float* Wb = W + (size_t)blockIdx.x * 128 * KDIM;

    const int r = tid >> 2;            // 0..63
    const int q = tid & 3;             // float4 slot in 16-k chunk

    float4 av[2], wv[2];
    auto g_load = [&](int k0) {
        #pragma unroll
        for (int i = 0; i < 2; i++) {
            int rr = i*64 + r;
            float4 v = *(const float4*)(Ab + (size_t)rr*KDIM + k0 + q*4);
            if (TRANS_A) {
                int kb = k0 + q*4;
                v.x = fmaxf(fmaf(v.x, sSc[kb+0], sSh[kb+0]), 0.0f);
                v.y = fmaxf(fmaf(v.y, sSc[kb+1], sSh[kb+1]), 0.0f);
                v.z = fmaxf(fmaf(v.z, sSc[kb+2], sSh[kb+2]), 0.0f);
                v.w = fmaxf(fmaf(v.w, sSc[kb+3], sSh[kb+3]), 0.0f);
            }
            av[i] = v;
            wv[i] = *(const float4*)(Wb + (size_t)rr*KDIM + k0 + q*4);
        }
    };
    auto s_store = [&](int buf) {
        float* base = tiles + buf * 10240;
        #pragma unroll
        for (int i = 0; i < 2; i++) {
            int rr = i*64 + r;
            uint32_t h[4], l[4];
            split_tf32(av[i].x, h[0], l[0]); split_tf32(av[i].y, h[1], l[1]);
            split_tf32(av[i].z, h[2], l[2]); split_tf32(av[i].w, h[3], l[3]);
            *(uint4*)(base +        rr*20 + q*4) = make_uint4(h[0],h[1],h[2],h[3]);
            *(uint4*)(base + 2560 + rr*20 + q*4) = make_uint4(l[0],l[1],l[2],l[3]);
            split_tf32(wv[i].x, h[0], l[0]); split_tf32(wv[i].y, h[1], l[1]);
            split_tf32(wv[i].z, h[2], l[2]); split_tf32(wv[i].w, h[3], l[3]);
            *(uint4*)(base + 5120 + rr*20 + q*4) = make_uint4(h[0],h[1],h[2],h[3]);
            *(uint4*)(base + 7680 + rr*20 + q*4) = make_uint4(l[0],l[1],l[2],l[3]);
        }
    };
    auto do_mma = [&](int buf) {
        const uint32_t* Ah = (const uint32_t*)(tiles + buf * 10240);
        const uint32_t* Al = Ah + 2560;
        const uint32_t* Bh = Ah + 5120;
        const uint32_t* Bl = Ah + 7680;
        #pragma unroll
        for (int ks = 0; ks < 2; ks++) {
            const int k = ks * 8;
            uint32_t ah[2][4], al[2][4], bh[8][2], bl[8][2];
            #pragma unroll
            for (int mt = 0; mt < 2; mt++) {
                int m0 = wm + mt*16;
                ah[mt][0] = Ah[(m0+g  )*20 + k+t  ];
                ah[mt][1] = Ah[(m0+g+8)*20 + k+t  ];
                ah[mt][2] = Ah[(m0+g  )*20 + k+t+4];
                ah[mt][3] = Ah[(m0+g+8)*20 + k+t+4];
                al[mt][0] = Al[(m0+g  )*20 + k+t  ];
                al[mt][1] = Al[(m0+g+8)*20 + k+t  ];
                al[mt][2] = Al[(m0+g  )*20 + k+t+4];
                al[mt][3] = Al[(m0+g+8)*20 + k+t+4];
            }
            #pragma unroll
            for (int nt = 0; nt < 8; nt++) {
                int n0 = wn + nt*8;
                bh[nt][0] = Bh[(n0+g)*20 + k+t  ];
                bh[nt][1] = Bh[(n0+g)*20 + k+t+4];
                bl[nt][0] = Bl[(n0+g)*20 + k+t  ];
                bl[nt][1] = Bl[(n0+g)*20 + k+t+4];
            }
            #pragma unroll
            for (int mt = 0; mt < 2; mt++)
                #pragma unroll
                for (int nt = 0; nt < 8; nt++) {
                    mma8(acc[mt][nt], ah[mt], bh[nt]);
                    mma8(acc[mt][nt], al[mt], bh[nt]);
                    mma8(acc[mt][nt], ah[mt], bl[nt]);
                }
        }
    };

    const int KT = KDIM / 16;
    g_load(0);
    s_store(0);
    __syncthreads();
    for (int kt = 0; kt < KT; kt++) {
        if (kt + 1 < KT) g_load((kt + 1) * 16);
        do_mma(kt & 1);
        if (kt + 1 < KT) {
            s_store((kt + 1) & 1);
            __syncthreads();
        }
    }

    // Epilogue: +bias, float2 stores
    #pragma unroll
    for (int mt = 0; mt < 2; mt++) {
        const int row0 = blockIdx.y*128 + wm + mt*16 + g;
        #pragma unroll
        for (int nt = 0; nt < 8; nt++) {
            const int col = blockIdx.x*128 + wn + nt*8 + 2*t;
            const float b0 = __ldg(&bias[col]), b1 = __ldg(&bias[col+1]);
            *(float2*)(Y + (size_t)row0 * N + col) =
                make_float2(acc[mt][nt][0] + b0, acc[mt][nt][1] + b1);
            *(float2*)(Y + (size_t)(row0+8) * N + col) =
                make_float2(acc[mt][nt][2] + b0, acc[mt][nt][3] + b1);
        }
    }
}

// ---------------------------------------------------------------------------
// BN stats stage 1: per-256-row-strip channel partial sum / sumsq over Y.
// grid = (N/64, RPARTS), block = 256 (= 64 channels x 4 row parts).
// ---------------------------------------------------------------------------
__global__ void stats_stage1(const float* __restrict__ Y, int N,
                             float* __restrict__ ps, float* __restrict__ pq)
{
    __shared__ float ss[4][64], sq[4][64];
    const int cl = threadIdx.x & 63, part = threadIdx.x >> 6;
    const int c = blockIdx.x * 64 + cl;
    const size_t r0 = (size_t)blockIdx.y * 256 + part * 64;
    float s0 = 0.f, q0 = 0.f, s1 = 0.f, q1 = 0.f;
    #pragma unroll 4
    for (int i = 0; i < 64; i += 2) {
        float v0 = Y[(r0 + i)     * N + c];
        float v1 = Y[(r0 + i + 1) * N + c];
        s0 += v0; q0 = fmaf(v0, v0, q0);
        s1 += v1; q1 = fmaf(v1, v1, q1);
    }
    ss[part][cl] = s0 + s1; sq[part][cl] = q0 + q1;
    __syncthreads();
    if (part == 0) {
        ps[(size_t)blockIdx.y * N + c] = (ss[0][cl]+ss[1][cl]) + (ss[2][cl]+ss[3][cl]);
        pq[(size_t)blockIdx.y * N + c] = (sq[0][cl]+sq[1][cl]) + (sq[2][cl]+sq[3][cl]);
    }
}

// ---------------------------------------------------------------------------
// BN stats stage 2: reduce RPARTS partials -> scale/shift per channel.
// ---------------------------------------------------------------------------
__global__ void bn_stats2(const float* __restrict__ ps, const float* __restrict__ pq,
                          int N, const float* __restrict__ g,
                          const float* __restrict__ beta,
                          float* __restrict__ scale, float* __restrict__ shift)
{
    __shared__ float ss[4][64], sq[4][64];
    const int cl = threadIdx.x & 63, part = threadIdx.x >> 6;
    const int c = blockIdx.x * 64 + cl;
    const int r0 = part * (RPARTS / 4);
    float s = 0.f, q = 0.f;
    #pragma unroll 4
    for (int r = 0; r < RPARTS / 4; r++) {
        s += ps[(size_t)(r0 + r) * N + c];
        q += pq[(size_t)(r0 + r) * N + c];
    }
    ss[part][cl] = s; sq[part][cl] = q;
    __syncthreads();
    if (part == 0) {
        double S = (double)ss[0][cl] + (double)ss[1][cl]
                 + (double)ss[2][cl] + (double)ss[3][cl];
        double Q = (double)sq[0][cl] + (double)sq[1][cl]
                 + (double)sq[2][cl] + (double)sq[3][cl];
        double mu  = S / (double)MROWS;
        double var = Q / (double)MROWS - mu * mu;
        float sc = g[c] / sqrtf((float)var + 1e-5f);
        scale[c] = sc;
        shift[c] = beta[c] - (float)mu * sc;
    }
}

// ---------------------------------------------------------------------------
// Final: out = relu(Y2 * scale2 + shift2)
// ---------------------------------------------------------------------------
__global__ void bn_relu_out_kernel(const float* __restrict__ Y,
                                   float* __restrict__ out)
{
    int i = blockIdx.x * blockDim.x + threadIdx.x;
    const float4 v = ((const float4*)Y)[i];
    int c = (i * 4) & (N2V - 1);
    float4 o;
    o.x = fmaxf(fmaf(v.x, g_sc2[c+0], g_sh2[c+0]), 0.0f);
    o.y = fmaxf(fmaf(v.y, g_sc2[c+1], g_sh2[c+1]), 0.0f);
    o.z = fmaxf(fmaf(v.z, g_sc2[c+2], g_sh2[c+2]), 0.0f);
    o.w = fmaxf(fmaf(v.w, g_sc2[c+3], g_sh2[c+3]), 0.0f);
    ((float4*)out)[i] = o;
}

// ---------------------------------------------------------------------------
// Launcher (graph-capturable)
// ---------------------------------------------------------------------------
extern "C" void kernel_launch(void* const* d_in, const int* in_sizes, int n_in,
                              void* d_out, int out_size)
{
    const float* xyz1    = (const float*)d_in[0];
    const float* xyz2    = (const float*)d_in[1];
    const float* points1 = (const float*)d_in[2];
    const float* points2 = (const float*)d_in[3];
    const float* w1      = (const float*)d_in[4];
    const float* b1      = (const float*)d_in[5];
    const float* g1      = (const float*)d_in[6];
    const float* beta1   = (const float*)d_in[7];
    const float* w2      = (const float*)d_in[8];
    const float* b2      = (const float*)d_in[9];
    const float* g2      = (const float*)d_in[10];
    const float* beta2   = (const float*)d_in[11];
    float* out = (float*)d_out;

    float *pX, *pY1, *pY2, *pps1, *ppq1, *pps2, *ppq2, *psc1, *psh1, *psc2, *psh2;
    cudaGetSymbolAddress((void**)&pX,   g_X);
    cudaGetSymbolAddress((void**)&pY1,  g_Y1);
    cudaGetSymbolAddress((void**)&pY2,  g_Y2);
    cudaGetSymbolAddress((void**)&pps1, g_ps1);
    cudaGetSymbolAddress((void**)&ppq1, g_pq1);
    cudaGetSymbolAddress((void**)&pps2, g_ps2);
    cudaGetSymbolAddress((void**)&ppq2, g_pq2);
    cudaGetSymbolAddress((void**)&psc1, g_sc1);
    cudaGetSymbolAddress((void**)&psh1, g_sh1);
    cudaGetSymbolAddress((void**)&psc2, g_sc2);
    cudaGetSymbolAddress((void**)&psh2, g_sh2);

    // dynamic smem: 768 floats (scale/shift) + 2 bufs * 4 arrays * 2560 floats
    const int SMEM = (768 + 2 * 4 * 2560) * 4;   // 84992 bytes
    cudaFuncSetAttribute(gemm_mma<K1V, false>,
                         cudaFuncAttributeMaxDynamicSharedMemorySize, SMEM);
    cudaFuncSetAttribute(gemm_mma<K2V, true>,
                         cudaFuncAttributeMaxDynamicSharedMemorySize, SMEM);

    nn3_kernel<<<dim3(NPTS/256, BATCH), 256>>>(xyz1, xyz2);
    gather_concat_kernel<<<MROWS/8, 256>>>(points1, points2);

    gemm_mma<K1V, false><<<dim3(N1V/128, MROWS/128), 256, SMEM>>>(
        pX, w1, b1, nullptr, nullptr, pY1, N1V);
    stats_stage1<<<dim3(N1V/64, RPARTS), 256>>>(pY1, N1V, pps1, ppq1);
    bn_stats2<<<N1V/64, 256>>>(pps1, ppq1, N1V, g1, beta1, psc1, psh1);

    gemm_mma<K2V, true><<<dim3(N2V/128, MROWS/128), 256, SMEM>>>(
        pY1, w2, b2, psc1, psh1, pY2, N2V);
    stats_stage1<<<dim3(N2V/64, RPARTS), 256>>>(pY2, N2V, pps2, ppq2);
    bn_stats2<<<N2V/64, 256>>>(pps2, ppq2, N2V, g2, beta2, psc2, psh2);

    bn_relu_out_kernel<<<(MROWS * N2V / 4) / 256, 256>>>(pY2, out);
}